// round 17
// baseline (speedup 1.0000x reference)
#include <cuda_runtime.h>
#include <math.h>

// Problem constants (fixed shapes per reference)
#define NFK 4096
#define NRK 8192
#define NTH 256
#define FCH 64                  // f columns per tile
#define NCH (NFK/FCH)           // 64 f-chunks

// rot tiles: 256 threads, 4 r/thread -> 1024 r per tile
#define RT_NT 4
#define RT_RBLK (NTH*RT_NT)     // 1024
#define RT_NRB (NRK/RT_RBLK)    // 8
#define RT_TILES (NCH*RT_NRB)   // 512

// trans tiles: 256 threads, 8 r/thread -> 2048 r per tile
#define TR_NT 8
#define TR_RBLK (NTH*TR_NT)     // 2048
#define TR_NRB (NRK/TR_RBLK)    // 4
#define TR_TILES (NCH*TR_NRB)   // 256

#define QBLK 48                 // quat blocks: 48*256 = NRK+NFK exactly
#define PRE_GRID (QBLK + TR_TILES)   // 304: quat + trans in one launch
#define EBLK 48                 // epilogue blocks: 48*256 = NRK+NFK exactly

#define EPS_CH   1e-5f
#define EPS_ACOS 1e-6f
#define PI_F     3.14159265358979323846f

// ---------------- static device scratch (allocation-free) ----------------
// Encodings (reset value 0 = "no update"; epilogue re-zeros each replay):
//   g_ru[r]  = max of ~bits(min_f w)   -> w = squared translation distance >= 0
//   g_fv[f]  = max of ~bits(min_r w)
//   g_rtr[r] = max of  bits(max_f s)   -> s = (q_f . q_r)^2 in [0,1]; trace = 4s-1
//   g_ftr[f] = max of  bits(max_r s)
__device__ unsigned g_done;            // finisher election counter (monotonic)
__device__ unsigned g_ru[NRK];
__device__ unsigned g_rtr[NRK];
__device__ unsigned g_fv[NFK];
__device__ unsigned g_ftr[NFK];
__device__ float    g_psum[4][EBLK];   // SoA per-epilogue-block partial sums
__device__ float4   g_qr[NRK];         // quaternions of r_buffer (recomputed per run)
__device__ float4   g_qf[NFK];         // quaternions of R_fake

// ---------------- packed f32x2 helpers ----------------
__device__ __forceinline__ unsigned long long pk2(float a, float b) {
    unsigned long long r;
    asm("mov.b64 %0, {%1, %2};" : "=l"(r) : "f"(a), "f"(b));
    return r;
}
__device__ __forceinline__ void unpk2(unsigned long long v, float& lo, float& hi) {
    asm("mov.b64 {%0, %1}, %2;" : "=f"(lo), "=f"(hi) : "l"(v));
}
__device__ __forceinline__ unsigned long long ffma2(unsigned long long a,
                                                    unsigned long long b,
                                                    unsigned long long c) {
    unsigned long long d;
    asm("fma.rn.f32x2 %0, %1, %2, %3;" : "=l"(d) : "l"(a), "l"(b), "l"(c));
    return d;
}
__device__ __forceinline__ unsigned long long fmul2(unsigned long long a,
                                                    unsigned long long b) {
    unsigned long long d;
    asm("mul.rn.f32x2 %0, %1, %2;" : "=l"(d) : "l"(a), "l"(b));
    return d;
}
__device__ __forceinline__ unsigned long long fadd2(unsigned long long a,
                                                    unsigned long long b) {
    unsigned long long d;
    asm("add.rn.f32x2 %0, %1, %2;" : "=l"(d) : "l"(a), "l"(b));
    return d;
}

// ======== k1: quat conversion (blocks 0..QBLK) + trans tiles (rest) ========
__global__ __launch_bounds__(NTH, 3)
void pre_kernel(const float* __restrict__ t_fake,
                const float* __restrict__ R_fake,
                const float* __restrict__ r_buffer,
                const float* __restrict__ t_buffer) {
    __shared__ __align__(16) float    sf[FCH * 8];       // trans tile staging
    __shared__ __align__(16) unsigned s_fred[FCH][8];    // per-warp per-f results

    const int tid  = threadIdx.x;
    const int lane = tid & 31;
    const int warp = tid >> 5;

    if (blockIdx.x < QBLK) {
        // ---- quat conversion: division-free Shepperd + rsqrt normalize ----
        const int i = blockIdx.x * NTH + tid;        // 0 .. NRK+NFK-1
        const float* R;
        float4* dst;
        if (i < NRK) { R = r_buffer + (size_t)i * 9;        dst = &g_qr[i]; }
        else         { R = R_fake  + (size_t)(i - NRK) * 9; dst = &g_qf[i - NRK]; }

        float r00 = R[0], r01 = R[1], r02 = R[2];
        float r10 = R[3], r11 = R[4], r12 = R[5];
        float r20 = R[6], r21 = R[7], r22 = R[8];
        float t = r00 + r11 + r22;
        // unnormalized pivot quaternion (scale-free: only direction matters)
        float w, x, y, z;
        if (t > 0.0f) {
            w = 1.0f + t;       x = r21 - r12;      y = r02 - r20;      z = r10 - r01;
        } else if (r00 > r11 && r00 > r22) {
            w = r21 - r12;      x = 1.0f + r00 - r11 - r22;
            y = r01 + r10;      z = r02 + r20;
        } else if (r11 > r22) {
            w = r02 - r20;      x = r01 + r10;
            y = 1.0f + r11 - r00 - r22;             z = r12 + r21;
        } else {
            w = r10 - r01;      x = r02 + r20;
            y = r12 + r21;      z = 1.0f + r22 - r00 - r11;
        }
        float h = fmaf(w, w, fmaf(x, x, fmaf(y, y, z * z)));
        float n = rsqrtf(h);
        n = n * fmaf(-0.5f * h * n, n, 1.5f);       // one Newton step
        *dst = make_float4(w * n, x * n, y * n, z * n);
    } else {
        // ---------------- translation tile (R16, unchanged) ----------------
        const int bx = blockIdx.x - QBLK;
        const int cx = bx & (NCH - 1);
        const int ry = bx >> 6;
        const int fbase = cx * FCH;
        const int rbase = ry * TR_RBLK;

        if (tid < FCH) {
            int fg = fbase + tid;
            float tx = t_fake[fg*3+0], ty = t_fake[fg*3+1], tz = t_fake[fg*3+2];
            float nf = fmaf(tx, tx, fmaf(ty, ty, tz * tz));
            float* p = &sf[tid * 8];
            p[0] = tx; p[1] = tx; p[2] = ty; p[3] = ty;
            p[4] = tz; p[5] = tz; p[6] = nf; p[7] = nf;
        }

        const int r0 = rbase + tid * TR_NT;
        unsigned long long tb2[4][3], nr2[4];
        #pragma unroll
        for (int jp = 0; jp < 4; jp++) {
            int ra = r0 + 2 * jp, rb = ra + 1;
            float ax = t_buffer[ra*3+0], ay = t_buffer[ra*3+1], az = t_buffer[ra*3+2];
            float bx2 = t_buffer[rb*3+0], by = t_buffer[rb*3+1], bz = t_buffer[rb*3+2];
            tb2[jp][0] = pk2(ax, bx2);
            tb2[jp][1] = pk2(ay, by);
            tb2[jp][2] = pk2(az, bz);
            nr2[jp] = pk2(fmaf(ax, ax, fmaf(ay, ay, az * az)),
                          fmaf(bx2, bx2, fmaf(by, by, bz * bz)));
        }
        __syncthreads();

        const float INF = __int_as_float(0x7f800000);
        const unsigned long long M2 = pk2(-2.0f, -2.0f);
        float minw[TR_NT];
        #pragma unroll
        for (int j = 0; j < TR_NT; j++) minw[j] = INF;

        #pragma unroll 2
        for (int f = 0; f < FCH; f++) {
            const ulonglong2* fp = reinterpret_cast<const ulonglong2*>(sf + f * 8);
            ulonglong2 A = fp[0];   // tx2, ty2
            ulonglong2 B = fp[1];   // tz2, nf2

            float pm[4];
            #pragma unroll
            for (int jp = 0; jp < 4; jp++) {
                unsigned long long dot =
                    ffma2(tb2[jp][0], A.x, ffma2(tb2[jp][1], A.y, fmul2(tb2[jp][2], B.x)));
                unsigned long long w2 = fadd2(ffma2(dot, M2, B.y), nr2[jp]);
                float wl, wh;
                unpk2(w2, wl, wh);
                minw[2*jp+0] = fminf(minw[2*jp+0], wl);
                minw[2*jp+1] = fminf(minw[2*jp+1], wh);
                pm[jp] = fminf(wl, wh);
            }
            float fv = fminf(fminf(pm[0], pm[1]), fminf(pm[2], pm[3]));
            unsigned ev = __reduce_min_sync(0xffffffffu, __float_as_uint(fv));
            if (lane == 0) s_fred[f][warp] = ev;
        }

        #pragma unroll
        for (int j = 0; j < TR_NT; j++)
            atomicMax(&g_ru[r0 + j], ~__float_as_uint(minw[j]));

        __syncthreads();
        if (tid < FCH) {
            const uint4* p = reinterpret_cast<const uint4*>(&s_fred[tid][0]);
            uint4 a = p[0], b = p[1];
            unsigned ev = umin(umin(umin(a.x, a.y), umin(a.z, a.w)),
                               umin(umin(b.x, b.y), umin(b.z, b.w)));
            atomicMax(&g_fv[fbase + tid], ~ev);
        }
    }
}

// ======== k2: rotation tiles: s = (q_f . q_r)^2, 4-dim dot (R16) ========
__global__ __launch_bounds__(NTH, 3)
void rot_kernel() {
    __shared__ __align__(16) float    sf[FCH * 8];
    __shared__ __align__(16) unsigned s_fred[FCH][8];

    const int tid  = threadIdx.x;
    const int lane = tid & 31;
    const int warp = tid >> 5;

    const int cx = blockIdx.x & (NCH - 1);
    const int ry = blockIdx.x >> 6;
    const int fbase = cx * FCH;
    const int rbase = ry * RT_RBLK;

    // stage duplicated quat tile: one thread per f
    if (tid < FCH) {
        float4 q = g_qf[fbase + tid];
        float* p = &sf[tid * 8];
        p[0] = q.x; p[1] = q.x; p[2] = q.y; p[3] = q.y;
        p[4] = q.z; p[5] = q.z; p[6] = q.w; p[7] = q.w;
    }

    const int r0 = rbase + tid * RT_NT;
    unsigned long long Qr2[2][4];
    #pragma unroll
    for (int jp = 0; jp < 2; jp++) {
        float4 qa = g_qr[r0 + 2 * jp];
        float4 qb = g_qr[r0 + 2 * jp + 1];
        Qr2[jp][0] = pk2(qa.x, qb.x);
        Qr2[jp][1] = pk2(qa.y, qb.y);
        Qr2[jp][2] = pk2(qa.z, qb.z);
        Qr2[jp][3] = pk2(qa.w, qb.w);
    }
    __syncthreads();

    const float INF = __int_as_float(0x7f800000);
    float maxs[RT_NT];
    #pragma unroll
    for (int j = 0; j < RT_NT; j++) maxs[j] = -INF;

    #pragma unroll 2
    for (int f = 0; f < FCH; f++) {
        const ulonglong2* fp = reinterpret_cast<const ulonglong2*>(sf + f * 8);
        ulonglong2 A = fp[0];   // qw2, qx2
        ulonglong2 B = fp[1];   // qy2, qz2

        float ft = -INF;
        #pragma unroll
        for (int jp = 0; jp < 2; jp++) {
            unsigned long long d =
                ffma2(Qr2[jp][3], B.y,
                      ffma2(Qr2[jp][2], B.x,
                            ffma2(Qr2[jp][1], A.y, fmul2(Qr2[jp][0], A.x))));
            unsigned long long s2 = fmul2(d, d);   // s = d^2 >= 0
            float sl, sh;
            unpk2(s2, sl, sh);
            maxs[2*jp+0] = fmaxf(maxs[2*jp+0], sl);
            maxs[2*jp+1] = fmaxf(maxs[2*jp+1], sh);
            ft = fmaxf(ft, fmaxf(sl, sh));
        }
        unsigned et = __reduce_max_sync(0xffffffffu, __float_as_uint(ft));
        if (lane == 0) s_fred[f][warp] = et;
    }

    #pragma unroll
    for (int j = 0; j < RT_NT; j++)
        atomicMax(&g_rtr[r0 + j], __float_as_uint(maxs[j]));

    __syncthreads();
    if (tid < FCH) {
        const uint4* p = reinterpret_cast<const uint4*>(&s_fred[tid][0]);
        uint4 a = p[0], b = p[1];
        unsigned et = umax(umax(umax(a.x, a.y), umax(a.z, a.w)),
                           umax(umax(b.x, b.y), umax(b.z, b.w)));
        atomicMax(&g_ftr[fbase + tid], et);
    }
}

// ---------------- epilogue: 96KB read, sqrt/acos, fixed-order sum ----------------
__global__ __launch_bounds__(NTH, 4)
void epilogue_kernel(float* __restrict__ out) {
    const int tid = threadIdx.x;
    const int gid = blockIdx.x * NTH + tid;    // 0 .. NRK+NFK-1
    const int lane = tid & 31;
    const int warp = tid >> 5;

    float sAngR = 0.f, sSqR = 0.f, sAngF = 0.f, sSqF = 0.f;

    if (gid < NRK) {
        unsigned eu = g_ru[gid];
        unsigned et = g_rtr[gid];
        g_ru[gid] = 0u;
        g_rtr[gid] = 0u;
        float w = __uint_as_float(~eu);            // min squared distance
        sSqR = sqrtf(fmaxf(w, 0.0f) + EPS_CH);
        float s = __uint_as_float(et);             // max (qf.qr)^2; trace = 4s-1
        float cs = fmaf(2.0f, s, -1.0f);           // 0.5*(trace-1) = 2s-1
        cs = fminf(fmaxf(cs, -1.0f + EPS_ACOS), 1.0f - EPS_ACOS);
        sAngR = acosf(cs);
    } else {
        const int f = gid - NRK;
        unsigned ev = g_fv[f];
        unsigned et = g_ftr[f];
        g_fv[f] = 0u;
        g_ftr[f] = 0u;
        float w = __uint_as_float(~ev);
        sSqF = sqrtf(fmaxf(w, 0.0f) + EPS_CH);
        float s = __uint_as_float(et);
        float cs = fmaf(2.0f, s, -1.0f);
        cs = fminf(fmaxf(cs, -1.0f + EPS_ACOS), 1.0f - EPS_ACOS);
        sAngF = acosf(cs);
    }

    // fixed-tree block reduction (deterministic)
    #pragma unroll
    for (int off = 16; off; off >>= 1) {
        sAngR += __shfl_xor_sync(0xffffffffu, sAngR, off);
        sSqR  += __shfl_xor_sync(0xffffffffu, sSqR,  off);
        sAngF += __shfl_xor_sync(0xffffffffu, sAngF, off);
        sSqF  += __shfl_xor_sync(0xffffffffu, sSqF,  off);
    }
    __shared__ float s_buf[NTH/32][4];
    __shared__ int s_fin;
    if (lane == 0) {
        s_buf[warp][0] = sAngR; s_buf[warp][1] = sSqR;
        s_buf[warp][2] = sAngF; s_buf[warp][3] = sSqF;
    }
    __syncthreads();

    if (tid == 0) {
        float a0 = 0.f, a1 = 0.f, a2 = 0.f, a3 = 0.f;
        #pragma unroll
        for (int i = 0; i < NTH/32; i++) {
            a0 += s_buf[i][0]; a1 += s_buf[i][1]; a2 += s_buf[i][2]; a3 += s_buf[i][3];
        }
        g_psum[0][blockIdx.x] = a0;
        g_psum[1][blockIdx.x] = a1;
        g_psum[2][blockIdx.x] = a2;
        g_psum[3][blockIdx.x] = a3;
        __threadfence();
        unsigned old = atomicAdd(&g_done, 1u);
        s_fin = ((old % EBLK) == (EBLK - 1u));
    }
    __syncthreads();

    // finisher: lane-parallel fixed-tree combine of 48 partials (warp 0)
    if (s_fin && warp == 0) {
        __threadfence();                            // acquire all psum writes
        float c[4];
        #pragma unroll
        for (int comp = 0; comp < 4; comp++) {
            float s = (lane < EBLK) ? g_psum[comp][lane] : 0.f;
            if (lane < EBLK - 32) s += g_psum[comp][lane + 32];
            #pragma unroll
            for (int off = 16; off; off >>= 1)
                s += __shfl_xor_sync(0xffffffffu, s, off);
            c[comp] = s;
        }
        if (lane == 0) {
            float rloss = c[2] / (float)NFK + c[0] / (float)NRK;
            float tloss = c[1] / (float)NRK + c[3] / (float)NFK;
            out[0] = rloss + tloss * PI_F;
        }
    }
}

// ---------------- launch ----------------
extern "C" void kernel_launch(void* const* d_in, const int* in_sizes, int n_in,
                              void* d_out, int out_size) {
    const float* t_fake   = nullptr;  // 4096*3
    const float* R_fake   = nullptr;  // 4096*9
    const float* r_buffer = nullptr;  // 8192*9
    const float* t_buffer = nullptr;  // 8192*3
    for (int i = 0; i < n_in; i++) {
        switch (in_sizes[i]) {
            case NFK*3: t_fake   = (const float*)d_in[i]; break;
            case NFK*9: R_fake   = (const float*)d_in[i]; break;
            case NRK*9: r_buffer = (const float*)d_in[i]; break;
            case NRK*3: t_buffer = (const float*)d_in[i]; break;
            default: break;
        }
    }

    pre_kernel<<<PRE_GRID, NTH>>>(t_fake, R_fake, r_buffer, t_buffer);
    rot_kernel<<<RT_TILES, NTH>>>();
    epilogue_kernel<<<EBLK, NTH>>>((float*)d_out);
}